// round 15
// baseline (speedup 1.0000x reference)
#include <cuda_runtime.h>
#include <cuda_bf16.h>
#include <cuda_fp16.h>
#include <cstdint>

#define NB 16384

__device__ __half g_W1cat[3 * 288 * 1024];     // [g][n:288][k] fp16; n<256 W1, 256+ Wg (zero-pad)
__device__ __half g_W2p[3 * 4 * 256 * 64];     // W2 fp16 [g][e][d][k]
__device__ __half g_h[3ull * NB * 256];        // h fp16
__device__ float  g_gates[3ull * NB * 12];

__device__ __forceinline__ uint32_t smem_u32(const void* p) {
    uint32_t a;
    asm("{ .reg .u64 t; cvta.to.shared.u64 t, %1; cvt.u32.u64 %0, t; }" : "=r"(a) : "l"(p));
    return a;
}
__device__ __forceinline__ void cp16s(uint32_t dst, const void* src) {
    asm volatile("cp.async.cg.shared.global [%0], [%1], 16;\n" :: "r"(dst), "l"(src));
}
__device__ __forceinline__ void cp16(void* dst, const void* src) { cp16s(smem_u32(dst), src); }
__device__ __forceinline__ void cp_commit() { asm volatile("cp.async.commit_group;\n"); }
__device__ __forceinline__ void cp_wait0()  { asm volatile("cp.async.wait_group 0;\n"); }
__device__ __forceinline__ void cp_wait1()  { asm volatile("cp.async.wait_group 1;\n"); }

__device__ __forceinline__ void ldsm4(unsigned* r, uint32_t a) {
    asm volatile("ldmatrix.sync.aligned.m8n8.x4.shared.b16 {%0,%1,%2,%3}, [%4];"
        : "=r"(r[0]), "=r"(r[1]), "=r"(r[2]), "=r"(r[3]) : "r"(a));
}
__device__ __forceinline__ void ldsm2(unsigned* r, uint32_t a) {
    asm volatile("ldmatrix.sync.aligned.m8n8.x2.shared.b16 {%0,%1}, [%2];"
        : "=r"(r[0]), "=r"(r[1]) : "r"(a));
}
__device__ __forceinline__ void mma_f16(float* c, const unsigned* a, unsigned b0, unsigned b1) {
    asm volatile(
        "mma.sync.aligned.m16n8k16.row.col.f32.f16.f16.f32 "
        "{%0,%1,%2,%3}, {%4,%5,%6,%7}, {%8,%9}, {%0,%1,%2,%3};\n"
        : "+f"(c[0]), "+f"(c[1]), "+f"(c[2]), "+f"(c[3])
        : "r"(a[0]), "r"(a[1]), "r"(a[2]), "r"(a[3]), "r"(b0), "r"(b1));
}

// ---------- packs ----------
__global__ void pack_w1_kernel(const float* __restrict__ W1A, const float* __restrict__ W1S,
                               const float* __restrict__ W1B,
                               const float* __restrict__ WgA, const float* __restrict__ WgS,
                               const float* __restrict__ WgB)
{
    int idx = blockIdx.x * blockDim.x + threadIdx.x;
    if (idx >= 3 * 288 * 1024) return;
    int k = idx & 1023;
    int n = (idx >> 10) % 288;
    int g = idx / (288 * 1024);
    const float* W1 = (g == 0) ? W1A : (g == 1) ? W1S : W1B;
    const float* Wg = (g == 0) ? WgA : (g == 1) ? WgS : WgB;
    int G = (g == 1) ? 12 : 8;
    float w = 0.f;
    if (n < 256)            w = W1[((size_t)(n >> 6) * 1024 + k) * 64 + (n & 63)];
    else if (n < 256 + G)   w = Wg[(size_t)k * G + (n - 256)];
    g_W1cat[idx] = __float2half_rn(w);
}
__global__ void pack_w2_kernel(const float* __restrict__ W2A, const float* __restrict__ W2S,
                               const float* __restrict__ W2B)
{
    int idx = blockIdx.x * blockDim.x + threadIdx.x;
    if (idx >= 3 * 4 * 256 * 64) return;
    int k = idx & 63, d = (idx >> 6) & 255, e = (idx >> 14) & 3, g = idx >> 16;
    const float* W2 = (g == 0) ? W2A : (g == 1) ? W2S : W2B;
    g_W2p[idx] = __float2half_rn(W2[((size_t)e * 64 + k) * 256 + d]);
}

// ---------- layer 1 + gate: fp16 HMMA, BM=128 BN=144 (2 N-CTAs), 2 CTAs/SM ----------
#define A_BUF 5120    // 128*40 halves
#define B_BUF 5760    // 144*40 halves
#define L1_SM 43520   // (2*5120 + 2*5760)*2 bytes

__global__ __launch_bounds__(256, 2)
void layer1_kernel(const float* __restrict__ xA, const float* __restrict__ xS,
                   const float* __restrict__ xB,
                   const float* __restrict__ b1A, const float* __restrict__ b1S,
                   const float* __restrict__ b1B,
                   const float* __restrict__ bgA, const float* __restrict__ bgS,
                   const float* __restrict__ bgB)
{
    extern __shared__ __half sm1[];
    __half* sA = sm1;                // 2 x 5120
    __half* sB = sm1 + 10240;        // 2 x 5760

    const int tid = threadIdx.x;
    const int g = blockIdx.z;
    const int nb = blockIdx.y;       // N half: 0 -> cols 0..143, 1 -> cols 144..287
    const int row0 = blockIdx.x * 128;
    const float* x  = (g == 0) ? xA  : (g == 1) ? xS  : xB;
    const float* b1 = (g == 0) ? b1A : (g == 1) ? b1S : b1B;
    const float* bg = (g == 0) ? bgA : (g == 1) ? bgS : bgB;
    const int G = (g == 1) ? 12 : 8;
    const __half* Wp = g_W1cat + (size_t)g * 288 * 1024 + (size_t)nb * 144 * 1024;

    const int lane = tid & 31, wid = tid >> 5;
    const int gid = lane >> 2, quad = lane & 3;
    const int wm = wid & 3, wn = wid >> 2;   // 4 x M32, 2 x N72
    const int a_row = (lane & 7) + ((lane >> 3) & 1) * 8;
    const int a_col = (lane >> 4) * 8;
    const int b_row = (lane & 7) + (lane >> 4) * 8;
    const int b_col = ((lane >> 3) & 1) * 8;
    const int b2_row = lane & 7;
    const int b2_col = ((lane >> 3) & 1) * 8;

    float acc[2][9][4];
    #pragma unroll
    for (int mt = 0; mt < 2; mt++)
        #pragma unroll
        for (int nt = 0; nt < 9; nt++)
            #pragma unroll
            for (int q = 0; q < 4; q++) acc[mt][nt][q] = 0.f;

    float4 areg[4];
    auto loadA = [&](int kt) {
        int k0 = kt * 32;
        #pragma unroll
        for (int i = 0; i < 4; i++) {
            int idx = tid + i * 256;       // 0..1023
            int r = idx >> 3, c = idx & 7;
            areg[i] = *reinterpret_cast<const float4*>(x + (size_t)(row0 + r) * 1024 + k0 + c * 4);
        }
    };
    auto storeA = [&](int buf) {
        #pragma unroll
        for (int i = 0; i < 4; i++) {
            int idx = tid + i * 256;
            int r = idx >> 3, c = idx & 7;
            float4 f = areg[i];
            __half2 H0; H0.x = __float2half_rn(f.x); H0.y = __float2half_rn(f.y);
            __half2 H1; H1.x = __float2half_rn(f.z); H1.y = __float2half_rn(f.w);
            int off = buf * A_BUF + r * 40 + c * 4;
            reinterpret_cast<__half2*>(sA + off)[0] = H0;
            reinterpret_cast<__half2*>(sA + off)[1] = H1;
        }
    };
    auto loadB = [&](int kt, int buf) {
        int k0 = kt * 32;
        #pragma unroll
        for (int i = 0; i < 3; i++) {
            int idx = tid + i * 256;       // 0..575 (144*4)
            if (idx < 576) {
                int n = idx >> 2, c = idx & 3;
                cp16(sB + buf * B_BUF + n * 40 + c * 8, Wp + (size_t)n * 1024 + k0 + c * 8);
            }
        }
    };
    auto compute = [&](int buf) {
        const __half* Ah = sA + buf * A_BUF;
        const __half* Bh = sB + buf * B_BUF;
        #pragma unroll
        for (int ks = 0; ks < 2; ks++) {
            int kb = ks * 16;
            unsigned ah[2][4];
            #pragma unroll
            for (int mt = 0; mt < 2; mt++) {
                int r = wm * 32 + mt * 16 + a_row;
                ldsm4(ah[mt], smem_u32(Ah + r * 40 + kb + a_col));
            }
            #pragma unroll
            for (int bt = 0; bt < 4; bt++) {
                int n = wn * 72 + bt * 16 + b_row;
                unsigned bh[4];
                ldsm4(bh, smem_u32(Bh + n * 40 + kb + b_col));
                #pragma unroll
                for (int mt = 0; mt < 2; mt++) {
                    mma_f16(acc[mt][2 * bt],     ah[mt], bh[0], bh[1]);
                    mma_f16(acc[mt][2 * bt + 1], ah[mt], bh[2], bh[3]);
                }
            }
            {   // remainder 8-col tile (nt=8)
                int n = wn * 72 + 64 + b2_row;
                unsigned br[2];
                ldsm2(br, smem_u32(Bh + n * 40 + kb + b2_col));
                #pragma unroll
                for (int mt = 0; mt < 2; mt++)
                    mma_f16(acc[mt][8], ah[mt], br[0], br[1]);
            }
        }
    };

    loadA(0);
    loadB(0, 0);
    cp_commit();
    storeA(0);
    cp_wait0();
    __syncthreads();

    #pragma unroll 1
    for (int kt = 0; kt < 32; kt++) {
        int buf = kt & 1;
        if (kt < 31) {
            loadA(kt + 1);
            loadB(kt + 1, buf ^ 1);
            cp_commit();
        }
        compute(buf);
        if (kt < 31) {
            storeA(buf ^ 1);
            cp_wait0();
        }
        __syncthreads();
    }

    // epilogue 1: h (global cols < 256) -> fp16 store with bias+relu
    __half* Hp = g_h + (size_t)g * NB * 256;
    #pragma unroll
    for (int mt = 0; mt < 2; mt++) {
        #pragma unroll
        for (int nt = 0; nt < 9; nt++) {
            int col = nb * 144 + wn * 72 + nt * 8 + quad * 2;
            if (col < 256) {
                float2 bv = *reinterpret_cast<const float2*>(b1 + col);
                #pragma unroll
                for (int p = 0; p < 2; p++) {
                    int row = row0 + wm * 32 + mt * 16 + gid + p * 8;
                    float v0 = fmaxf(acc[mt][nt][p * 2 + 0] + bv.x, 0.f);
                    float v1 = fmaxf(acc[mt][nt][p * 2 + 1] + bv.y, 0.f);
                    __half2 PH; PH.x = __float2half_rn(v0); PH.y = __float2half_rn(v1);
                    *reinterpret_cast<__half2*>(Hp + (size_t)row * 256 + col) = PH;
                }
            }
        }
    }

    // epilogue 2: gate logits (global cols 256..287 -> nb==1, wn==1, nt 5..8)
    if (nb == 1) {
        __syncthreads();
        float* slog = reinterpret_cast<float*>(sm1);   // [128][33]
        if (wn == 1) {
            #pragma unroll
            for (int mt = 0; mt < 2; mt++) {
                #pragma unroll
                for (int nt = 5; nt < 9; nt++) {
                    int c = nt * 8 - 40 + quad * 2;    // 0..31
                    #pragma unroll
                    for (int p = 0; p < 2; p++) {
                        int rl = wm * 32 + mt * 16 + gid + p * 8;
                        slog[rl * 33 + c]     = acc[mt][nt][p * 2 + 0];
                        slog[rl * 33 + c + 1] = acc[mt][nt][p * 2 + 1];
                    }
                }
            }
        }
        __syncthreads();
        if (tid < 128) {
            float lg[12], m = -1e30f;
            for (int j = 0; j < G; j++) { lg[j] = slog[tid * 33 + j] + bg[j]; m = fmaxf(m, lg[j]); }
            float s = 0.f;
            for (int j = 0; j < G; j++) { lg[j] = expf(lg[j] - m); s += lg[j]; }
            float inv = 1.f / s;
            float* dst = g_gates + ((size_t)g * NB + row0 + tid) * 12;
            for (int j = 0; j < G; j++) dst[j] = lg[j] * inv;
        }
    }
}

// ---------- layer 2 + combine: fp16 1-term, fully unrolled ge loop ----------
#define L2_SM 46080

__global__ __launch_bounds__(256, 1)
void layer2_kernel(const float* __restrict__ b2A, const float* __restrict__ b2S,
                   const float* __restrict__ b2B, float* __restrict__ out)
{
    extern __shared__ char sm2[];
    __half* shb = reinterpret_cast<__half*>(sm2);
    __half* swb = reinterpret_cast<__half*>(sm2 + 18432);
    float* sg = reinterpret_cast<float*>(sm2 + 36864);

    const int tid = threadIdx.x;
    const int d0 = blockIdx.x * 64;
    const int row0 = blockIdx.y * 64;
    const int lane = tid & 31, wid = tid >> 5;
    const int gid = lane >> 2, quad = lane & 3;
    const int wm = wid & 1, wn = wid >> 1;

    const int a_row = (lane & 7) + ((lane >> 3) & 1) * 8;
    const int a_col = (lane >> 4) * 8;
    const int b_row = (lane & 7) + (lane >> 4) * 8;
    const int b_col = ((lane >> 3) & 1) * 8;

    for (int i = tid; i < 3 * 64 * 12; i += 256) {
        int gg = i / 768, r = (i / 12) & 63, j = i % 12;
        sg[(gg * 64 + r) * 12 + j] = g_gates[((size_t)gg * NB + row0 + r) * 12 + j];
    }

    int rq[4];
    #pragma unroll
    for (int q = 0; q < 4; q++) rq[q] = wm * 32 + (q >> 1) * 16 + gid + (q & 1) * 8;

    auto prefetch = [&](int ge, int s) {
        int g = ge >> 2, e = ge & 3;
        const __half* Hp = g_h + (size_t)g * NB * 256;
        const __half* Wp2 = g_W2p + ((size_t)(g * 4 + e) * 256 + d0) * 64;
        __half* shs = shb + s * 4608;
        __half* sws = swb + s * 4608;
        #pragma unroll
        for (int i = 0; i < 2; i++) {
            int idx = tid + i * 256;
            int r = idx >> 3, c = idx & 7;
            cp16(shs + r * 72 + c * 8, Hp + (size_t)(row0 + r) * 256 + e * 64 + c * 8);
            cp16(sws + r * 72 + c * 8, Wp2 + (size_t)r * 64 + c * 8);
        }
        cp_commit();
    };

    float oA[2][2][4], oS[2][2][4], oB[2][2][4];
    #pragma unroll
    for (int mt = 0; mt < 2; mt++)
        #pragma unroll
        for (int nt = 0; nt < 2; nt++)
            #pragma unroll
            for (int q = 0; q < 4; q++) { oA[mt][nt][q] = 0.f; oS[mt][nt][q] = 0.f; oB[mt][nt][q] = 0.f; }

    prefetch(0, 0);
    __syncthreads();

    #pragma unroll
    for (int ge = 0; ge < 12; ge++) {
        const int s = ge & 1;
        const int g = ge >> 2, e = ge & 3;
        if (ge < 11) { prefetch(ge + 1, s ^ 1); cp_wait1(); }
        else cp_wait0();
        __syncthreads();

        const __half* shs = shb + s * 4608;
        const __half* sws = swb + s * 4608;

        float t[2][2][4];
        #pragma unroll
        for (int mt = 0; mt < 2; mt++)
            #pragma unroll
            for (int nt = 0; nt < 2; nt++)
                #pragma unroll
                for (int q = 0; q < 4; q++) t[mt][nt][q] = 0.f;

        #pragma unroll
        for (int ks = 0; ks < 4; ks++) {
            int kb = ks * 16;
            unsigned ah[2][4];
            #pragma unroll
            for (int mt = 0; mt < 2; mt++) {
                int r = wm * 32 + mt * 16 + a_row;
                ldsm4(ah[mt], smem_u32(shs + r * 72 + kb + a_col));
            }
            int n = wn * 16 + b_row;
            unsigned bh[4];
            ldsm4(bh, smem_u32(sws + n * 72 + kb + b_col));
            #pragma unroll
            for (int mt = 0; mt < 2; mt++) {
                mma_f16(t[mt][0], ah[mt], bh[0], bh[1]);
                mma_f16(t[mt][1], ah[mt], bh[2], bh[3]);
            }
        }

        // static-g gate loads (branches fold at compile time under full unroll)
        float gA4[4], gS4[4], gB4[4];
        #pragma unroll
        for (int q = 0; q < 4; q++) {
            int rr = rq[q];
            if (g == 0) {
                gA4[q] = sg[(0 * 64 + rr) * 12 + e];
                gS4[q] = sg[(1 * 64 + rr) * 12 + e];
            } else if (g == 1) {
                gA4[q] = sg[(0 * 64 + rr) * 12 + 4 + e];
                gS4[q] = sg[(1 * 64 + rr) * 12 + 4 + e];
                gB4[q] = sg[(2 * 64 + rr) * 12 + 4 + e];
            } else {
                gS4[q] = sg[(1 * 64 + rr) * 12 + 8 + e];
                gB4[q] = sg[(2 * 64 + rr) * 12 + e];
            }
        }

        const float* b2 = (g == 0) ? b2A : (g == 1) ? b2S : b2B;
        #pragma unroll
        for (int mt = 0; mt < 2; mt++) {
            #pragma unroll
            for (int nt = 0; nt < 2; nt++) {
                int col = wn * 16 + nt * 8 + quad * 2;
                float2 bv = *reinterpret_cast<const float2*>(b2 + e * 256 + d0 + col);
                #pragma unroll
                for (int p = 0; p < 2; p++) {
                    int q = mt * 2 + p;
                    float v0 = fmaxf(t[mt][nt][p * 2 + 0] + bv.x, 0.f);
                    float v1 = fmaxf(t[mt][nt][p * 2 + 1] + bv.y, 0.f);
                    if (g == 0 || g == 1) {
                        oA[mt][nt][p * 2 + 0] += gA4[q] * v0;
                        oA[mt][nt][p * 2 + 1] += gA4[q] * v1;
                    }
                    oS[mt][nt][p * 2 + 0] += gS4[q] * v0;
                    oS[mt][nt][p * 2 + 1] += gS4[q] * v1;
                    if (g == 1 || g == 2) {
                        oB[mt][nt][p * 2 + 0] += gB4[q] * v0;
                        oB[mt][nt][p * 2 + 1] += gB4[q] * v1;
                    }
                }
            }
        }
        __syncthreads();
    }

    #pragma unroll
    for (int mt = 0; mt < 2; mt++) {
        #pragma unroll
        for (int nt = 0; nt < 2; nt++) {
            int col = d0 + wn * 16 + nt * 8 + quad * 2;
            #pragma unroll
            for (int p = 0; p < 2; p++) {
                int row = row0 + wm * 32 + mt * 16 + gid + p * 8;
                size_t base = (size_t)row * 256 + col;
                float2 vA; vA.x = oA[mt][nt][p * 2]; vA.y = oA[mt][nt][p * 2 + 1];
                float2 vS; vS.x = oS[mt][nt][p * 2]; vS.y = oS[mt][nt][p * 2 + 1];
                float2 vB; vB.x = oB[mt][nt][p * 2]; vB.y = oB[mt][nt][p * 2 + 1];
                *reinterpret_cast<float2*>(out + base) = vA;
                *reinterpret_cast<float2*>(out + (size_t)NB * 256 + base) = vS;
                *reinterpret_cast<float2*>(out + 2ull * NB * 256 + base) = vB;
            }
        }
    }
}

extern "C" void kernel_launch(void* const* d_in, const int* in_sizes, int n_in,
                              void* d_out, int out_size)
{
    const float* xA  = (const float*)d_in[0];
    const float* xS  = (const float*)d_in[1];
    const float* xB  = (const float*)d_in[2];
    const float* W1A = (const float*)d_in[3];
    const float* b1A = (const float*)d_in[4];
    const float* W2A = (const float*)d_in[5];
    const float* b2A = (const float*)d_in[6];
    const float* W1S = (const float*)d_in[7];
    const float* b1S = (const float*)d_in[8];
    const float* W2S = (const float*)d_in[9];
    const float* b2S = (const float*)d_in[10];
    const float* W1B = (const float*)d_in[11];
    const float* b1B = (const float*)d_in[12];
    const float* W2B = (const float*)d_in[13];
    const float* b2B = (const float*)d_in[14];
    const float* WgA = (const float*)d_in[15];
    const float* bgA = (const float*)d_in[16];
    const float* WgB = (const float*)d_in[17];
    const float* bgB = (const float*)d_in[18];
    const float* WgS = (const float*)d_in[19];
    const float* bgS = (const float*)d_in[20];
    float* out = (float*)d_out;

    pack_w1_kernel<<<(3 * 288 * 1024 + 255) / 256, 256>>>(W1A, W1S, W1B, WgA, WgS, WgB);
    pack_w2_kernel<<<(3 * 4 * 256 * 64 + 255) / 256, 256>>>(W2A, W2S, W2B);

    cudaFuncSetAttribute(layer1_kernel, cudaFuncAttributeMaxDynamicSharedMemorySize, L1_SM);
    layer1_kernel<<<dim3(NB / 128, 2, 3), 256, L1_SM>>>(xA, xS, xB, b1A, b1S, b1B, bgA, bgS, bgB);

    cudaFuncSetAttribute(layer2_kernel, cudaFuncAttributeMaxDynamicSharedMemorySize, L2_SM);
    layer2_kernel<<<dim3(256 / 64, NB / 64), 256, L2_SM>>>(b2A, b2S, b2B, out);
}

// round 16
// speedup vs baseline: 1.0079x; 1.0079x over previous
#include <cuda_runtime.h>
#include <cuda_bf16.h>
#include <cuda_fp16.h>
#include <cstdint>

#define NB 16384

__device__ __half g_W1cat[3 * 288 * 1024];     // [g][n:288][k] fp16; n<256 W1, 256+ Wg (zero-pad)
__device__ __half g_W2p[3 * 4 * 256 * 64];     // W2 fp16 [g][e][d][k]
__device__ __half g_h[3ull * NB * 256];        // h fp16
__device__ float  g_gates[3ull * NB * 12];

__device__ __forceinline__ uint32_t smem_u32(const void* p) {
    uint32_t a;
    asm("{ .reg .u64 t; cvta.to.shared.u64 t, %1; cvt.u32.u64 %0, t; }" : "=r"(a) : "l"(p));
    return a;
}
__device__ __forceinline__ void cp16s(uint32_t dst, const void* src) {
    asm volatile("cp.async.cg.shared.global [%0], [%1], 16;\n" :: "r"(dst), "l"(src));
}
__device__ __forceinline__ void cp16(void* dst, const void* src) { cp16s(smem_u32(dst), src); }
__device__ __forceinline__ void cp_commit() { asm volatile("cp.async.commit_group;\n"); }
__device__ __forceinline__ void cp_wait0()  { asm volatile("cp.async.wait_group 0;\n"); }
__device__ __forceinline__ void cp_wait1()  { asm volatile("cp.async.wait_group 1;\n"); }

__device__ __forceinline__ void ldsm4(unsigned* r, uint32_t a) {
    asm volatile("ldmatrix.sync.aligned.m8n8.x4.shared.b16 {%0,%1,%2,%3}, [%4];"
        : "=r"(r[0]), "=r"(r[1]), "=r"(r[2]), "=r"(r[3]) : "r"(a));
}
__device__ __forceinline__ void ldsm2(unsigned* r, uint32_t a) {
    asm volatile("ldmatrix.sync.aligned.m8n8.x2.shared.b16 {%0,%1}, [%2];"
        : "=r"(r[0]), "=r"(r[1]) : "r"(a));
}
__device__ __forceinline__ void mma_f16(float* c, const unsigned* a, unsigned b0, unsigned b1) {
    asm volatile(
        "mma.sync.aligned.m16n8k16.row.col.f32.f16.f16.f32 "
        "{%0,%1,%2,%3}, {%4,%5,%6,%7}, {%8,%9}, {%0,%1,%2,%3};\n"
        : "+f"(c[0]), "+f"(c[1]), "+f"(c[2]), "+f"(c[3])
        : "r"(a[0]), "r"(a[1]), "r"(a[2]), "r"(a[3]), "r"(b0), "r"(b1));
}

// ---------- packs ----------
__global__ void pack_w1_kernel(const float* __restrict__ W1A, const float* __restrict__ W1S,
                               const float* __restrict__ W1B,
                               const float* __restrict__ WgA, const float* __restrict__ WgS,
                               const float* __restrict__ WgB)
{
    int idx = blockIdx.x * blockDim.x + threadIdx.x;
    if (idx >= 3 * 288 * 1024) return;
    int k = idx & 1023;
    int n = (idx >> 10) % 288;
    int g = idx / (288 * 1024);
    const float* W1 = (g == 0) ? W1A : (g == 1) ? W1S : W1B;
    const float* Wg = (g == 0) ? WgA : (g == 1) ? WgS : WgB;
    int G = (g == 1) ? 12 : 8;
    float w = 0.f;
    if (n < 256)            w = W1[((size_t)(n >> 6) * 1024 + k) * 64 + (n & 63)];
    else if (n < 256 + G)   w = Wg[(size_t)k * G + (n - 256)];
    g_W1cat[idx] = __float2half_rn(w);
}
__global__ void pack_w2_kernel(const float* __restrict__ W2A, const float* __restrict__ W2S,
                               const float* __restrict__ W2B)
{
    int idx = blockIdx.x * blockDim.x + threadIdx.x;
    if (idx >= 3 * 4 * 256 * 64) return;
    int k = idx & 63, d = (idx >> 6) & 255, e = (idx >> 14) & 3, g = idx >> 16;
    const float* W2 = (g == 0) ? W2A : (g == 1) ? W2S : W2B;
    g_W2p[idx] = __float2half_rn(W2[((size_t)e * 64 + k) * 256 + d]);
}

// ---------- layer 1 + gate: fp16 HMMA, BM=128 BN=144 (2 N-CTAs), 2 CTAs/SM ----------
#define A_BUF 5120    // 128*40 halves
#define B_BUF 5760    // 144*40 halves
#define L1_SM 43520

__global__ __launch_bounds__(256, 2)
void layer1_kernel(const float* __restrict__ xA, const float* __restrict__ xS,
                   const float* __restrict__ xB,
                   const float* __restrict__ b1A, const float* __restrict__ b1S,
                   const float* __restrict__ b1B,
                   const float* __restrict__ bgA, const float* __restrict__ bgS,
                   const float* __restrict__ bgB)
{
    extern __shared__ __half sm1[];
    __half* sA = sm1;                // 2 x 5120
    __half* sB = sm1 + 10240;        // 2 x 5760

    const int tid = threadIdx.x;
    const int g = blockIdx.z;
    const int nb = blockIdx.y;       // N half: 0 -> cols 0..143, 1 -> cols 144..287
    const int row0 = blockIdx.x * 128;
    const float* x  = (g == 0) ? xA  : (g == 1) ? xS  : xB;
    const float* b1 = (g == 0) ? b1A : (g == 1) ? b1S : b1B;
    const float* bg = (g == 0) ? bgA : (g == 1) ? bgS : bgB;
    const int G = (g == 1) ? 12 : 8;
    const __half* Wp = g_W1cat + (size_t)g * 288 * 1024 + (size_t)nb * 144 * 1024;

    const int lane = tid & 31, wid = tid >> 5;
    const int gid = lane >> 2, quad = lane & 3;
    const int wm = wid & 3, wn = wid >> 2;   // 4 x M32, 2 x N72
    const int a_row = (lane & 7) + ((lane >> 3) & 1) * 8;
    const int a_col = (lane >> 4) * 8;
    const int b_row = (lane & 7) + (lane >> 4) * 8;
    const int b_col = ((lane >> 3) & 1) * 8;
    const int b2_row = lane & 7;
    const int b2_col = ((lane >> 3) & 1) * 8;

    float acc[2][9][4];
    #pragma unroll
    for (int mt = 0; mt < 2; mt++)
        #pragma unroll
        for (int nt = 0; nt < 9; nt++)
            #pragma unroll
            for (int q = 0; q < 4; q++) acc[mt][nt][q] = 0.f;

    float4 areg[4];
    auto loadA = [&](int kt) {
        int k0 = kt * 32;
        #pragma unroll
        for (int i = 0; i < 4; i++) {
            int idx = tid + i * 256;
            int r = idx >> 3, c = idx & 7;
            areg[i] = *reinterpret_cast<const float4*>(x + (size_t)(row0 + r) * 1024 + k0 + c * 4);
        }
    };
    auto storeA = [&](int buf) {
        #pragma unroll
        for (int i = 0; i < 4; i++) {
            int idx = tid + i * 256;
            int r = idx >> 3, c = idx & 7;
            float4 f = areg[i];
            __half2 H0; H0.x = __float2half_rn(f.x); H0.y = __float2half_rn(f.y);
            __half2 H1; H1.x = __float2half_rn(f.z); H1.y = __float2half_rn(f.w);
            int off = buf * A_BUF + r * 40 + c * 4;
            reinterpret_cast<__half2*>(sA + off)[0] = H0;
            reinterpret_cast<__half2*>(sA + off)[1] = H1;
        }
    };
    auto loadB = [&](int kt, int buf) {
        int k0 = kt * 32;
        #pragma unroll
        for (int i = 0; i < 3; i++) {
            int idx = tid + i * 256;
            if (idx < 576) {
                int n = idx >> 2, c = idx & 3;
                cp16(sB + buf * B_BUF + n * 40 + c * 8, Wp + (size_t)n * 1024 + k0 + c * 8);
            }
        }
    };
    auto compute = [&](int buf) {
        const __half* Ah = sA + buf * A_BUF;
        const __half* Bh = sB + buf * B_BUF;
        #pragma unroll
        for (int ks = 0; ks < 2; ks++) {
            int kb = ks * 16;
            unsigned ah[2][4];
            #pragma unroll
            for (int mt = 0; mt < 2; mt++) {
                int r = wm * 32 + mt * 16 + a_row;
                ldsm4(ah[mt], smem_u32(Ah + r * 40 + kb + a_col));
            }
            #pragma unroll
            for (int bt = 0; bt < 4; bt++) {
                int n = wn * 72 + bt * 16 + b_row;
                unsigned bh[4];
                ldsm4(bh, smem_u32(Bh + n * 40 + kb + b_col));
                #pragma unroll
                for (int mt = 0; mt < 2; mt++) {
                    mma_f16(acc[mt][2 * bt],     ah[mt], bh[0], bh[1]);
                    mma_f16(acc[mt][2 * bt + 1], ah[mt], bh[2], bh[3]);
                }
            }
            {
                int n = wn * 72 + 64 + b2_row;
                unsigned br[2];
                ldsm2(br, smem_u32(Bh + n * 40 + kb + b2_col));
                #pragma unroll
                for (int mt = 0; mt < 2; mt++)
                    mma_f16(acc[mt][8], ah[mt], br[0], br[1]);
            }
        }
    };

    loadA(0);
    loadB(0, 0);
    cp_commit();
    storeA(0);
    cp_wait0();
    __syncthreads();

    #pragma unroll 1
    for (int kt = 0; kt < 32; kt++) {
        int buf = kt & 1;
        if (kt < 31) {
            loadA(kt + 1);
            loadB(kt + 1, buf ^ 1);
            cp_commit();
        }
        compute(buf);
        if (kt < 31) {
            storeA(buf ^ 1);
            cp_wait0();
        }
        __syncthreads();
    }

    __half* Hp = g_h + (size_t)g * NB * 256;
    #pragma unroll
    for (int mt = 0; mt < 2; mt++) {
        #pragma unroll
        for (int nt = 0; nt < 9; nt++) {
            int col = nb * 144 + wn * 72 + nt * 8 + quad * 2;
            if (col < 256) {
                float2 bv = *reinterpret_cast<const float2*>(b1 + col);
                #pragma unroll
                for (int p = 0; p < 2; p++) {
                    int row = row0 + wm * 32 + mt * 16 + gid + p * 8;
                    float v0 = fmaxf(acc[mt][nt][p * 2 + 0] + bv.x, 0.f);
                    float v1 = fmaxf(acc[mt][nt][p * 2 + 1] + bv.y, 0.f);
                    __half2 PH; PH.x = __float2half_rn(v0); PH.y = __float2half_rn(v1);
                    *reinterpret_cast<__half2*>(Hp + (size_t)row * 256 + col) = PH;
                }
            }
        }
    }

    if (nb == 1) {
        __syncthreads();
        float* slog = reinterpret_cast<float*>(sm1);   // [128][33]
        if (wn == 1) {
            #pragma unroll
            for (int mt = 0; mt < 2; mt++) {
                #pragma unroll
                for (int nt = 5; nt < 9; nt++) {
                    int c = nt * 8 - 40 + quad * 2;
                    #pragma unroll
                    for (int p = 0; p < 2; p++) {
                        int rl = wm * 32 + mt * 16 + gid + p * 8;
                        slog[rl * 33 + c]     = acc[mt][nt][p * 2 + 0];
                        slog[rl * 33 + c + 1] = acc[mt][nt][p * 2 + 1];
                    }
                }
            }
        }
        __syncthreads();
        if (tid < 128) {
            float lg[12], m = -1e30f;
            for (int j = 0; j < G; j++) { lg[j] = slog[tid * 33 + j] + bg[j]; m = fmaxf(m, lg[j]); }
            float s = 0.f;
            for (int j = 0; j < G; j++) { lg[j] = expf(lg[j] - m); s += lg[j]; }
            float inv = 1.f / s;
            float* dst = g_gates + ((size_t)g * NB + row0 + tid) * 12;
            for (int j = 0; j < G; j++) dst[j] = lg[j] * inv;
        }
    }
}

// ---------- layer 2 + combine: fp16 1-term, precomputed gate-triple table ----------
// smem: shb 2x4608h (18432B), swb 2x4608h (18432B), sgx [12][64][4] floats (12288B)
#define L2_SM 49152

__global__ __launch_bounds__(256, 1)
void layer2_kernel(const float* __restrict__ b2A, const float* __restrict__ b2S,
                   const float* __restrict__ b2B, float* __restrict__ out)
{
    extern __shared__ char sm2[];
    __half* shb = reinterpret_cast<__half*>(sm2);
    __half* swb = reinterpret_cast<__half*>(sm2 + 18432);
    float* sgx = reinterpret_cast<float*>(sm2 + 36864);   // [12][64][4] = {gA,gS,gB,0}

    const int tid = threadIdx.x;
    const int d0 = blockIdx.x * 64;
    const int row0 = blockIdx.y * 64;
    const int lane = tid & 31, wid = tid >> 5;
    const int gid = lane >> 2, quad = lane & 3;
    const int wm = wid & 1, wn = wid >> 1;

    const int a_row = (lane & 7) + ((lane >> 3) & 1) * 8;
    const int a_col = (lane >> 4) * 8;
    const int b_row = (lane & 7) + (lane >> 4) * 8;
    const int b_col = ((lane >> 3) & 1) * 8;

    // one-time gate-triple table: branches run here, never in the mainloop
    for (int i = tid; i < 12 * 64; i += 256) {
        int ge = i >> 6, r = i & 63;
        int g = ge >> 2, e = ge & 3;
        const float* G0 = g_gates + ((size_t)0 * NB + row0 + r) * 12;
        const float* G1 = g_gates + ((size_t)1 * NB + row0 + r) * 12;
        const float* G2 = g_gates + ((size_t)2 * NB + row0 + r) * 12;
        float ga = 0.f, gs = 0.f, gb = 0.f;
        if (g == 0)      { ga = G0[e];     gs = G1[e]; }
        else if (g == 1) { ga = G0[4 + e]; gs = G1[4 + e]; gb = G2[4 + e]; }
        else             { gs = G1[8 + e]; gb = G2[e]; }
        float4 v; v.x = ga; v.y = gs; v.z = gb; v.w = 0.f;
        *reinterpret_cast<float4*>(sgx + i * 4) = v;
    }

    int rq[4];
    #pragma unroll
    for (int q = 0; q < 4; q++) rq[q] = wm * 32 + (q >> 1) * 16 + gid + (q & 1) * 8;

    auto prefetch = [&](int ge, int s) {
        int g = ge >> 2, e = ge & 3;
        const __half* Hp = g_h + (size_t)g * NB * 256;
        const __half* Wp2 = g_W2p + ((size_t)(g * 4 + e) * 256 + d0) * 64;
        __half* shs = shb + s * 4608;
        __half* sws = swb + s * 4608;
        #pragma unroll
        for (int i = 0; i < 2; i++) {
            int idx = tid + i * 256;
            int r = idx >> 3, c = idx & 7;
            cp16(shs + r * 72 + c * 8, Hp + (size_t)(row0 + r) * 256 + e * 64 + c * 8);
            cp16(sws + r * 72 + c * 8, Wp2 + (size_t)r * 64 + c * 8);
        }
        cp_commit();
    };

    float oA[2][2][4], oS[2][2][4], oB[2][2][4];
    #pragma unroll
    for (int mt = 0; mt < 2; mt++)
        #pragma unroll
        for (int nt = 0; nt < 2; nt++)
            #pragma unroll
            for (int q = 0; q < 4; q++) { oA[mt][nt][q] = 0.f; oS[mt][nt][q] = 0.f; oB[mt][nt][q] = 0.f; }

    prefetch(0, 0);
    __syncthreads();

    #pragma unroll 1
    for (int ge = 0; ge < 12; ge++) {
        int s = ge & 1;
        int g = ge >> 2, e = ge & 3;
        if (ge < 11) { prefetch(ge + 1, s ^ 1); cp_wait1(); }
        else cp_wait0();
        __syncthreads();

        const __half* shs = shb + s * 4608;
        const __half* sws = swb + s * 4608;

        float t[2][2][4];
        #pragma unroll
        for (int mt = 0; mt < 2; mt++)
            #pragma unroll
            for (int nt = 0; nt < 2; nt++)
                #pragma unroll
                for (int q = 0; q < 4; q++) t[mt][nt][q] = 0.f;

        #pragma unroll
        for (int ks = 0; ks < 4; ks++) {
            int kb = ks * 16;
            unsigned ah[2][4];
            #pragma unroll
            for (int mt = 0; mt < 2; mt++) {
                int r = wm * 32 + mt * 16 + a_row;
                ldsm4(ah[mt], smem_u32(shs + r * 72 + kb + a_col));
            }
            int n = wn * 16 + b_row;
            unsigned bh[4];
            ldsm4(bh, smem_u32(sws + n * 72 + kb + b_col));
            #pragma unroll
            for (int mt = 0; mt < 2; mt++) {
                mma_f16(t[mt][0], ah[mt], bh[0], bh[1]);
                mma_f16(t[mt][1], ah[mt], bh[2], bh[3]);
            }
        }

        // gate triples: one LDS.128 per thread-row, no branches
        float4 gv[4];
        const float* sgbase = sgx + (ge << 8);   // ge*64*4
        #pragma unroll
        for (int q = 0; q < 4; q++)
            gv[q] = *reinterpret_cast<const float4*>(sgbase + rq[q] * 4);

        const float* b2 = (g == 0) ? b2A : (g == 1) ? b2S : b2B;
        #pragma unroll
        for (int mt = 0; mt < 2; mt++) {
            #pragma unroll
            for (int nt = 0; nt < 2; nt++) {
                int col = wn * 16 + nt * 8 + quad * 2;
                float2 bv = *reinterpret_cast<const float2*>(b2 + e * 256 + d0 + col);
                #pragma unroll
                for (int p = 0; p < 2; p++) {
                    int q = mt * 2 + p;
                    float v0 = fmaxf(t[mt][nt][p * 2 + 0] + bv.x, 0.f);
                    float v1 = fmaxf(t[mt][nt][p * 2 + 1] + bv.y, 0.f);
                    oA[mt][nt][p * 2 + 0] += gv[q].x * v0; oA[mt][nt][p * 2 + 1] += gv[q].x * v1;
                    oS[mt][nt][p * 2 + 0] += gv[q].y * v0; oS[mt][nt][p * 2 + 1] += gv[q].y * v1;
                    oB[mt][nt][p * 2 + 0] += gv[q].z * v0; oB[mt][nt][p * 2 + 1] += gv[q].z * v1;
                }
            }
        }
        __syncthreads();
    }

    #pragma unroll
    for (int mt = 0; mt < 2; mt++) {
        #pragma unroll
        for (int nt = 0; nt < 2; nt++) {
            int col = d0 + wn * 16 + nt * 8 + quad * 2;
            #pragma unroll
            for (int p = 0; p < 2; p++) {
                int row = row0 + wm * 32 + mt * 16 + gid + p * 8;
                size_t base = (size_t)row * 256 + col;
                float2 vA; vA.x = oA[mt][nt][p * 2]; vA.y = oA[mt][nt][p * 2 + 1];
                float2 vS; vS.x = oS[mt][nt][p * 2]; vS.y = oS[mt][nt][p * 2 + 1];
                float2 vB; vB.x = oB[mt][nt][p * 2]; vB.y = oB[mt][nt][p * 2 + 1];
                *reinterpret_cast<float2*>(out + base) = vA;
                *reinterpret_cast<float2*>(out + (size_t)NB * 256 + base) = vS;
                *reinterpret_cast<float2*>(out + 2ull * NB * 256 + base) = vB;
            }
        }
    }
}

extern "C" void kernel_launch(void* const* d_in, const int* in_sizes, int n_in,
                              void* d_out, int out_size)
{
    const float* xA  = (const float*)d_in[0];
    const float* xS  = (const float*)d_in[1];
    const float* xB  = (const float*)d_in[2];
    const float* W1A = (const float*)d_in[3];
    const float* b1A = (const float*)d_in[4];
    const float* W2A = (const float*)d_in[5];
    const float* b2A = (const float*)d_in[6];
    const float* W1S = (const float*)d_in[7];
    const float* b1S = (const float*)d_in[8];
    const float* W2S = (const float*)d_in[9];
    const float* b2S = (const float*)d_in[10];
    const float* W1B = (const float*)d_in[11];
    const float* b1B = (const float*)d_in[12];
    const float* W2B = (const float*)d_in[13];
    const float* b2B = (const float*)d_in[14];
    const float* WgA = (const float*)d_in[15];
    const float* bgA = (const float*)d_in[16];
    const float* WgB = (const float*)d_in[17];
    const float* bgB = (const float*)d_in[18];
    const float* WgS = (const float*)d_in[19];
    const float* bgS = (const float*)d_in[20];
    float* out = (float*)d_out;

    pack_w1_kernel<<<(3 * 288 * 1024 + 255) / 256, 256>>>(W1A, W1S, W1B, WgA, WgS, WgB);
    pack_w2_kernel<<<(3 * 4 * 256 * 64 + 255) / 256, 256>>>(W2A, W2S, W2B);

    cudaFuncSetAttribute(layer1_kernel, cudaFuncAttributeMaxDynamicSharedMemorySize, L1_SM);
    layer1_kernel<<<dim3(NB / 128, 2, 3), 256, L1_SM>>>(xA, xS, xB, b1A, b1S, b1B, bgA, bgS, bgB);

    cudaFuncSetAttribute(layer2_kernel, cudaFuncAttributeMaxDynamicSharedMemorySize, L2_SM);
    layer2_kernel<<<dim3(256 / 64, NB / 64), 256, L2_SM>>>(b2A, b2S, b2B, out);
}

// round 17
// speedup vs baseline: 1.1090x; 1.1003x over previous
#include <cuda_runtime.h>
#include <cuda_bf16.h>
#include <cuda_fp16.h>
#include <cstdint>

#define NB 16384

__device__ __half g_W1cat[3 * 288 * 1024];     // [g][n:288][k] fp16; n<256 W1, 256+ Wg (zero-pad)
__device__ __half g_W2p[3 * 4 * 256 * 64];     // W2 fp16 [g][e][d][k]
__device__ __half g_h[3ull * NB * 256];        // h fp16
__device__ float  g_gates[3ull * NB * 12];

__device__ __forceinline__ uint32_t smem_u32(const void* p) {
    uint32_t a;
    asm("{ .reg .u64 t; cvta.to.shared.u64 t, %1; cvt.u32.u64 %0, t; }" : "=r"(a) : "l"(p));
    return a;
}
__device__ __forceinline__ void cp16s(uint32_t dst, const void* src) {
    asm volatile("cp.async.cg.shared.global [%0], [%1], 16;\n" :: "r"(dst), "l"(src));
}
__device__ __forceinline__ void cp16(void* dst, const void* src) { cp16s(smem_u32(dst), src); }
__device__ __forceinline__ void cp_commit() { asm volatile("cp.async.commit_group;\n"); }
__device__ __forceinline__ void cp_wait0()  { asm volatile("cp.async.wait_group 0;\n"); }
__device__ __forceinline__ void cp_wait1()  { asm volatile("cp.async.wait_group 1;\n"); }

__device__ __forceinline__ void ldsm4(unsigned* r, uint32_t a) {
    asm volatile("ldmatrix.sync.aligned.m8n8.x4.shared.b16 {%0,%1,%2,%3}, [%4];"
        : "=r"(r[0]), "=r"(r[1]), "=r"(r[2]), "=r"(r[3]) : "r"(a));
}
__device__ __forceinline__ void ldsm2(unsigned* r, uint32_t a) {
    asm volatile("ldmatrix.sync.aligned.m8n8.x2.shared.b16 {%0,%1}, [%2];"
        : "=r"(r[0]), "=r"(r[1]) : "r"(a));
}
__device__ __forceinline__ void mma_f16(float* c, const unsigned* a, unsigned b0, unsigned b1) {
    asm volatile(
        "mma.sync.aligned.m16n8k16.row.col.f32.f16.f16.f32 "
        "{%0,%1,%2,%3}, {%4,%5,%6,%7}, {%8,%9}, {%0,%1,%2,%3};\n"
        : "+f"(c[0]), "+f"(c[1]), "+f"(c[2]), "+f"(c[3])
        : "r"(a[0]), "r"(a[1]), "r"(a[2]), "r"(a[3]), "r"(b0), "r"(b1));
}

// ---------- packs ----------
__global__ void pack_w1_kernel(const float* __restrict__ W1A, const float* __restrict__ W1S,
                               const float* __restrict__ W1B,
                               const float* __restrict__ WgA, const float* __restrict__ WgS,
                               const float* __restrict__ WgB)
{
    int idx = blockIdx.x * blockDim.x + threadIdx.x;
    if (idx >= 3 * 288 * 1024) return;
    int k = idx & 1023;
    int n = (idx >> 10) % 288;
    int g = idx / (288 * 1024);
    const float* W1 = (g == 0) ? W1A : (g == 1) ? W1S : W1B;
    const float* Wg = (g == 0) ? WgA : (g == 1) ? WgS : WgB;
    int G = (g == 1) ? 12 : 8;
    float w = 0.f;
    if (n < 256)            w = W1[((size_t)(n >> 6) * 1024 + k) * 64 + (n & 63)];
    else if (n < 256 + G)   w = Wg[(size_t)k * G + (n - 256)];
    g_W1cat[idx] = __float2half_rn(w);
}
__global__ void pack_w2_kernel(const float* __restrict__ W2A, const float* __restrict__ W2S,
                               const float* __restrict__ W2B)
{
    int idx = blockIdx.x * blockDim.x + threadIdx.x;
    if (idx >= 3 * 4 * 256 * 64) return;
    int k = idx & 63, d = (idx >> 6) & 255, e = (idx >> 14) & 3, g = idx >> 16;
    const float* W2 = (g == 0) ? W2A : (g == 1) ? W2S : W2B;
    g_W2p[idx] = __float2half_rn(W2[((size_t)e * 64 + k) * 256 + d]);
}

// ---------- layer 1 + gate: fp16 HMMA, BM=128 BN=144 (2 N-CTAs), 2 CTAs/SM ----------
#define A_BUF 5120    // 128*40 halves
#define B_BUF 5760    // 144*40 halves
#define L1_SM 43520

__global__ __launch_bounds__(256, 2)
void layer1_kernel(const float* __restrict__ xA, const float* __restrict__ xS,
                   const float* __restrict__ xB,
                   const float* __restrict__ b1A, const float* __restrict__ b1S,
                   const float* __restrict__ b1B,
                   const float* __restrict__ bgA, const float* __restrict__ bgS,
                   const float* __restrict__ bgB)
{
    extern __shared__ __half sm1[];
    __half* sA = sm1;                // 2 x 5120
    __half* sB = sm1 + 10240;        // 2 x 5760

    const int tid = threadIdx.x;
    const int g = blockIdx.z;
    const int nb = blockIdx.y;       // N half: 0 -> cols 0..143, 1 -> cols 144..287
    const int row0 = blockIdx.x * 128;
    const float* x  = (g == 0) ? xA  : (g == 1) ? xS  : xB;
    const float* b1 = (g == 0) ? b1A : (g == 1) ? b1S : b1B;
    const float* bg = (g == 0) ? bgA : (g == 1) ? bgS : bgB;
    const int G = (g == 1) ? 12 : 8;
    const __half* Wp = g_W1cat + (size_t)g * 288 * 1024 + (size_t)nb * 144 * 1024;

    const int lane = tid & 31, wid = tid >> 5;
    const int gid = lane >> 2, quad = lane & 3;
    const int wm = wid & 3, wn = wid >> 2;   // 4 x M32, 2 x N72
    const int a_row = (lane & 7) + ((lane >> 3) & 1) * 8;
    const int a_col = (lane >> 4) * 8;
    const int b_row = (lane & 7) + (lane >> 4) * 8;
    const int b_col = ((lane >> 3) & 1) * 8;
    const int b2_row = lane & 7;
    const int b2_col = ((lane >> 3) & 1) * 8;

    float acc[2][9][4];
    #pragma unroll
    for (int mt = 0; mt < 2; mt++)
        #pragma unroll
        for (int nt = 0; nt < 9; nt++)
            #pragma unroll
            for (int q = 0; q < 4; q++) acc[mt][nt][q] = 0.f;

    float4 areg[4];
    auto loadA = [&](int kt) {
        int k0 = kt * 32;
        #pragma unroll
        for (int i = 0; i < 4; i++) {
            int idx = tid + i * 256;
            int r = idx >> 3, c = idx & 7;
            areg[i] = *reinterpret_cast<const float4*>(x + (size_t)(row0 + r) * 1024 + k0 + c * 4);
        }
    };
    auto storeA = [&](int buf) {
        #pragma unroll
        for (int i = 0; i < 4; i++) {
            int idx = tid + i * 256;
            int r = idx >> 3, c = idx & 7;
            float4 f = areg[i];
            __half2 H0; H0.x = __float2half_rn(f.x); H0.y = __float2half_rn(f.y);
            __half2 H1; H1.x = __float2half_rn(f.z); H1.y = __float2half_rn(f.w);
            int off = buf * A_BUF + r * 40 + c * 4;
            reinterpret_cast<__half2*>(sA + off)[0] = H0;
            reinterpret_cast<__half2*>(sA + off)[1] = H1;
        }
    };
    auto loadB = [&](int kt, int buf) {
        int k0 = kt * 32;
        #pragma unroll
        for (int i = 0; i < 3; i++) {
            int idx = tid + i * 256;
            if (idx < 576) {
                int n = idx >> 2, c = idx & 3;
                cp16(sB + buf * B_BUF + n * 40 + c * 8, Wp + (size_t)n * 1024 + k0 + c * 8);
            }
        }
    };
    auto compute = [&](int buf) {
        const __half* Ah = sA + buf * A_BUF;
        const __half* Bh = sB + buf * B_BUF;
        #pragma unroll
        for (int ks = 0; ks < 2; ks++) {
            int kb = ks * 16;
            unsigned ah[2][4];
            #pragma unroll
            for (int mt = 0; mt < 2; mt++) {
                int r = wm * 32 + mt * 16 + a_row;
                ldsm4(ah[mt], smem_u32(Ah + r * 40 + kb + a_col));
            }
            #pragma unroll
            for (int bt = 0; bt < 4; bt++) {
                int n = wn * 72 + bt * 16 + b_row;
                unsigned bh[4];
                ldsm4(bh, smem_u32(Bh + n * 40 + kb + b_col));
                #pragma unroll
                for (int mt = 0; mt < 2; mt++) {
                    mma_f16(acc[mt][2 * bt],     ah[mt], bh[0], bh[1]);
                    mma_f16(acc[mt][2 * bt + 1], ah[mt], bh[2], bh[3]);
                }
            }
            {
                int n = wn * 72 + 64 + b2_row;
                unsigned br[2];
                ldsm2(br, smem_u32(Bh + n * 40 + kb + b2_col));
                #pragma unroll
                for (int mt = 0; mt < 2; mt++)
                    mma_f16(acc[mt][8], ah[mt], br[0], br[1]);
            }
        }
    };

    loadA(0);
    loadB(0, 0);
    cp_commit();
    storeA(0);
    cp_wait0();
    __syncthreads();

    #pragma unroll 1
    for (int kt = 0; kt < 32; kt++) {
        int buf = kt & 1;
        if (kt < 31) {
            loadA(kt + 1);
            loadB(kt + 1, buf ^ 1);
            cp_commit();
        }
        compute(buf);
        if (kt < 31) {
            storeA(buf ^ 1);
            cp_wait0();
        }
        __syncthreads();
    }

    __half* Hp = g_h + (size_t)g * NB * 256;
    #pragma unroll
    for (int mt = 0; mt < 2; mt++) {
        #pragma unroll
        for (int nt = 0; nt < 9; nt++) {
            int col = nb * 144 + wn * 72 + nt * 8 + quad * 2;
            if (col < 256) {
                float2 bv = *reinterpret_cast<const float2*>(b1 + col);
                #pragma unroll
                for (int p = 0; p < 2; p++) {
                    int row = row0 + wm * 32 + mt * 16 + gid + p * 8;
                    float v0 = fmaxf(acc[mt][nt][p * 2 + 0] + bv.x, 0.f);
                    float v1 = fmaxf(acc[mt][nt][p * 2 + 1] + bv.y, 0.f);
                    __half2 PH; PH.x = __float2half_rn(v0); PH.y = __float2half_rn(v1);
                    *reinterpret_cast<__half2*>(Hp + (size_t)row * 256 + col) = PH;
                }
            }
        }
    }

    if (nb == 1) {
        __syncthreads();
        float* slog = reinterpret_cast<float*>(sm1);   // [128][33]
        if (wn == 1) {
            #pragma unroll
            for (int mt = 0; mt < 2; mt++) {
                #pragma unroll
                for (int nt = 5; nt < 9; nt++) {
                    int c = nt * 8 - 40 + quad * 2;
                    #pragma unroll
                    for (int p = 0; p < 2; p++) {
                        int rl = wm * 32 + mt * 16 + gid + p * 8;
                        slog[rl * 33 + c]     = acc[mt][nt][p * 2 + 0];
                        slog[rl * 33 + c + 1] = acc[mt][nt][p * 2 + 1];
                    }
                }
            }
        }
        __syncthreads();
        if (tid < 128) {
            float lg[12], m = -1e30f;
            for (int j = 0; j < G; j++) { lg[j] = slog[tid * 33 + j] + bg[j]; m = fmaxf(m, lg[j]); }
            float s = 0.f;
            for (int j = 0; j < G; j++) { lg[j] = expf(lg[j] - m); s += lg[j]; }
            float inv = 1.f / s;
            float* dst = g_gates + ((size_t)g * NB + row0 + tid) * 12;
            for (int j = 0; j < G; j++) dst[j] = lg[j] * inv;
        }
    }
}

// ---------- layer 2 + combine: fp16 1-term, compact gate-triple table (46080 B total) ----------
// smem: shb 2x4608h (18432B) @0, swb 2x4608h (18432B) @18432, sgx [12][64][3] fp32 (9216B) @36864
#define L2_SM 46080

__global__ __launch_bounds__(256, 1)
void layer2_kernel(const float* __restrict__ b2A, const float* __restrict__ b2S,
                   const float* __restrict__ b2B, float* __restrict__ out)
{
    extern __shared__ char sm2[];
    __half* shb = reinterpret_cast<__half*>(sm2);
    __half* swb = reinterpret_cast<__half*>(sm2 + 18432);
    float* sgx = reinterpret_cast<float*>(sm2 + 36864);   // [12][64][3] = {gA,gS,gB}

    const int tid = threadIdx.x;
    const int d0 = blockIdx.x * 64;
    const int row0 = blockIdx.y * 64;
    const int lane = tid & 31, wid = tid >> 5;
    const int gid = lane >> 2, quad = lane & 3;
    const int wm = wid & 1, wn = wid >> 1;

    const int a_row = (lane & 7) + ((lane >> 3) & 1) * 8;
    const int a_col = (lane >> 4) * 8;
    const int b_row = (lane & 7) + (lane >> 4) * 8;
    const int b_col = ((lane >> 3) & 1) * 8;

    // one-time gate-triple table: all branch logic here, never in the mainloop
    for (int i = tid; i < 12 * 64; i += 256) {
        int ge = i >> 6, r = i & 63;
        int g = ge >> 2, e = ge & 3;
        const float* G0 = g_gates + ((size_t)0 * NB + row0 + r) * 12;
        const float* G1 = g_gates + ((size_t)1 * NB + row0 + r) * 12;
        const float* G2 = g_gates + ((size_t)2 * NB + row0 + r) * 12;
        float ga = 0.f, gs = 0.f, gb = 0.f;
        if (g == 0)      { ga = G0[e];     gs = G1[e]; }
        else if (g == 1) { ga = G0[4 + e]; gs = G1[4 + e]; gb = G2[4 + e]; }
        else             { gs = G1[8 + e]; gb = G2[e]; }
        sgx[i * 3 + 0] = ga;
        sgx[i * 3 + 1] = gs;
        sgx[i * 3 + 2] = gb;
    }

    int rq[4];
    #pragma unroll
    for (int q = 0; q < 4; q++) rq[q] = wm * 32 + (q >> 1) * 16 + gid + (q & 1) * 8;

    auto prefetch = [&](int ge, int s) {
        int g = ge >> 2, e = ge & 3;
        const __half* Hp = g_h + (size_t)g * NB * 256;
        const __half* Wp2 = g_W2p + ((size_t)(g * 4 + e) * 256 + d0) * 64;
        __half* shs = shb + s * 4608;
        __half* sws = swb + s * 4608;
        #pragma unroll
        for (int i = 0; i < 2; i++) {
            int idx = tid + i * 256;
            int r = idx >> 3, c = idx & 7;
            cp16(shs + r * 72 + c * 8, Hp + (size_t)(row0 + r) * 256 + e * 64 + c * 8);
            cp16(sws + r * 72 + c * 8, Wp2 + (size_t)r * 64 + c * 8);
        }
        cp_commit();
    };

    float oA[2][2][4], oS[2][2][4], oB[2][2][4];
    #pragma unroll
    for (int mt = 0; mt < 2; mt++)
        #pragma unroll
        for (int nt = 0; nt < 2; nt++)
            #pragma unroll
            for (int q = 0; q < 4; q++) { oA[mt][nt][q] = 0.f; oS[mt][nt][q] = 0.f; oB[mt][nt][q] = 0.f; }

    prefetch(0, 0);
    __syncthreads();

    #pragma unroll 1
    for (int ge = 0; ge < 12; ge++) {
        int s = ge & 1;
        int g = ge >> 2, e = ge & 3;
        if (ge < 11) { prefetch(ge + 1, s ^ 1); cp_wait1(); }
        else cp_wait0();
        __syncthreads();

        const __half* shs = shb + s * 4608;
        const __half* sws = swb + s * 4608;

        float t[2][2][4];
        #pragma unroll
        for (int mt = 0; mt < 2; mt++)
            #pragma unroll
            for (int nt = 0; nt < 2; nt++)
                #pragma unroll
                for (int q = 0; q < 4; q++) t[mt][nt][q] = 0.f;

        #pragma unroll
        for (int ks = 0; ks < 4; ks++) {
            int kb = ks * 16;
            unsigned ah[2][4];
            #pragma unroll
            for (int mt = 0; mt < 2; mt++) {
                int r = wm * 32 + mt * 16 + a_row;
                ldsm4(ah[mt], smem_u32(shs + r * 72 + kb + a_col));
            }
            int n = wn * 16 + b_row;
            unsigned bh[4];
            ldsm4(bh, smem_u32(sws + n * 72 + kb + b_col));
            #pragma unroll
            for (int mt = 0; mt < 2; mt++) {
                mma_f16(t[mt][0], ah[mt], bh[0], bh[1]);
                mma_f16(t[mt][1], ah[mt], bh[2], bh[3]);
            }
        }

        // gate triples: 3 scalar LDS per thread-row, zero branches, zero index math in loop
        float gA4[4], gS4[4], gB4[4];
        const float* sgbase = sgx + ge * 192;   // 64*3
        #pragma unroll
        for (int q = 0; q < 4; q++) {
            const float* p = sgbase + rq[q] * 3;
            gA4[q] = p[0]; gS4[q] = p[1]; gB4[q] = p[2];
        }

        const float* b2 = (g == 0) ? b2A : (g == 1) ? b2S : b2B;
        #pragma unroll
        for (int mt = 0; mt < 2; mt++) {
            #pragma unroll
            for (int nt = 0; nt < 2; nt++) {
                int col = wn * 16 + nt * 8 + quad * 2;
                float2 bv = *reinterpret_cast<const float2*>(b2 + e * 256 + d0 + col);
                #pragma unroll
                for (int p = 0; p < 2; p++) {
                    int q = mt * 2 + p;
                    float v0 = fmaxf(t[mt][nt][p * 2 + 0] + bv.x, 0.f);
                    float v1 = fmaxf(t[mt][nt][p * 2 + 1] + bv.y, 0.f);
                    oA[mt][nt][p * 2 + 0] += gA4[q] * v0; oA[mt][nt][p * 2 + 1] += gA4[q] * v1;
                    oS[mt][nt][p * 2 + 0] += gS4[q] * v0; oS[mt][nt][p * 2 + 1] += gS4[q] * v1;
                    oB[mt][nt][p * 2 + 0] += gB4[q] * v0; oB[mt][nt][p * 2 + 1] += gB4[q] * v1;
                }
            }
        }
        __syncthreads();
    }

    #pragma unroll
    for (int mt = 0; mt < 2; mt++) {
        #pragma unroll
        for (int nt = 0; nt < 2; nt++) {
            int col = d0 + wn * 16 + nt * 8 + quad * 2;
            #pragma unroll
            for (int p = 0; p < 2; p++) {
                int row = row0 + wm * 32 + mt * 16 + gid + p * 8;
                size_t base = (size_t)row * 256 + col;
                float2 vA; vA.x = oA[mt][nt][p * 2]; vA.y = oA[mt][nt][p * 2 + 1];
                float2 vS; vS.x = oS[mt][nt][p * 2]; vS.y = oS[mt][nt][p * 2 + 1];
                float2 vB; vB.x = oB[mt][nt][p * 2]; vB.y = oB[mt][nt][p * 2 + 1];
                *reinterpret_cast<float2*>(out + base) = vA;
                *reinterpret_cast<float2*>(out + (size_t)NB * 256 + base) = vS;
                *reinterpret_cast<float2*>(out + 2ull * NB * 256 + base) = vB;
            }
        }
    }
}

extern "C" void kernel_launch(void* const* d_in, const int* in_sizes, int n_in,
                              void* d_out, int out_size)
{
    const float* xA  = (const float*)d_in[0];
    const float* xS  = (const float*)d_in[1];
    const float* xB  = (const float*)d_in[2];
    const float* W1A = (const float*)d_in[3];
    const float* b1A = (const float*)d_in[4];
    const float* W2A = (const float*)d_in[5];
    const float* b2A = (const float*)d_in[6];
    const float* W1S = (const float*)d_in[7];
    const float* b1S = (const float*)d_in[8];
    const float* W2S = (const float*)d_in[9];
    const float* b2S = (const float*)d_in[10];
    const float* W1B = (const float*)d_in[11];
    const float* b1B = (const float*)d_in[12];
    const float* W2B = (const float*)d_in[13];
    const float* b2B = (const float*)d_in[14];
    const float* WgA = (const float*)d_in[15];
    const float* bgA = (const float*)d_in[16];
    const float* WgB = (const float*)d_in[17];
    const float* bgB = (const float*)d_in[18];
    const float* WgS = (const float*)d_in[19];
    const float* bgS = (const float*)d_in[20];
    float* out = (float*)d_out;

    pack_w1_kernel<<<(3 * 288 * 1024 + 255) / 256, 256>>>(W1A, W1S, W1B, WgA, WgS, WgB);
    pack_w2_kernel<<<(3 * 4 * 256 * 64 + 255) / 256, 256>>>(W2A, W2S, W2B);

    cudaFuncSetAttribute(layer1_kernel, cudaFuncAttributeMaxDynamicSharedMemorySize, L1_SM);
    layer1_kernel<<<dim3(NB / 128, 2, 3), 256, L1_SM>>>(xA, xS, xB, b1A, b1S, b1B, bgA, bgS, bgB);

    cudaFuncSetAttribute(layer2_kernel, cudaFuncAttributeMaxDynamicSharedMemorySize, L2_SM);
    layer2_kernel<<<dim3(256 / 64, NB / 64), 256, L2_SM>>>(b2A, b2S, b2B, out);
}